// round 14
// baseline (speedup 1.0000x reference)
#include <cuda_runtime.h>
#include <cuda_bf16.h>

// Problem constants
#define BB   32
#define DD   256
#define NN   2304      // 48*48
#define HEADS 8
#define FB   1153      // NN/2+1
#define HF   (HEADS*FB)        // 9224
#define OUT2 (HEADS*FB*2)      // 18448

#define MLP2_SMEM ((DD*BB + 3*256*8) * 4)   // 57344 bytes

// ---------------- scratch ----------------
__device__ float  g_xh   [BB*DD*NN];   // [b][d][n]
__device__ float  g_yt   [BB*DD*NN];   // filtered, [b][d][n]
__device__ float  g_ctx  [BB*DD];      // raw sums (atomic), scaled in mlp1
__device__ float  g_hmidT[DD*BB];      // transposed: [o][b]
__device__ float  g_filt [BB*HF];
__device__ float  g_bias [BB*HF];
__device__ float2 g_tw   [NN];         // (cos, sin)(2*pi*j/2304)

typedef unsigned long long u64;

// ---------------- packed f32x2 helpers ----------------
__device__ __forceinline__ u64 pk2(float lo, float hi) {
    u64 r; asm("mov.b64 %0, {%1,%2};" : "=l"(r) : "f"(lo), "f"(hi)); return r;
}
__device__ __forceinline__ void upk2(u64 v, float& lo, float& hi) {
    asm("mov.b64 {%0,%1}, %2;" : "=f"(lo), "=f"(hi) : "l"(v));
}
__device__ __forceinline__ u64 f2fma(u64 a, u64 b, u64 c) {
    u64 d; asm("fma.rn.f32x2 %0, %1, %2, %3;" : "=l"(d) : "l"(a), "l"(b), "l"(c)); return d;
}
__device__ __forceinline__ u64 add2(u64 a, u64 b) {
    u64 d; asm("add.rn.f32x2 %0, %1, %2;" : "=l"(d) : "l"(a), "l"(b)); return d;
}
__device__ __forceinline__ u64 mul2(u64 a, u64 b) {
    u64 d; asm("mul.rn.f32x2 %0, %1, %2;" : "=l"(d) : "l"(a), "l"(b)); return d;
}
// tap-interleaved layout: taps (row&3) and col parity adjacent; 2496 floats total
__device__ __forceinline__ int L2i(int row, int col) {
    return (((row >> 2) * 26 + (col >> 1)) << 3) + ((row & 3) << 1) + (col & 1);
}

// ---------------- init: twiddles + zero ctx ----------------
__global__ void init_kernel() {
    int j = blockIdx.x * blockDim.x + threadIdx.x;   // 8192 threads
    if (j < NN) {
        float sv, cv;
        sincospif((float)j * (1.0f / 1152.0f), &sv, &cv);
        g_tw[j] = make_float2(cv, sv);
    }
    g_ctx[j] = 0.f;
}

// ---------------- fused LayerNorm + transpose + ctx partials ----------------
__global__ __launch_bounds__(256) void ln_t_kernel(const float* __restrict__ x,
                                                   const float* __restrict__ gamma,
                                                   const float* __restrict__ beta) {
    __shared__ float tile[32 * 257];
    __shared__ float smu[32], srs[32];
    int b  = blockIdx.y;
    int n0 = blockIdx.x * 32;
    int t  = threadIdx.x;

    const float* src = x + ((long)b * NN + n0) * DD;
    #pragma unroll
    for (int l = t; l < 32 * DD; l += 256) {
        int r = l >> 8, d = l & 255;
        tile[r * 257 + d] = src[l];
    }
    __syncthreads();

    int w = t >> 5, lane = t & 31;
    #pragma unroll
    for (int r = w; r < 32; r += 8) {
        float s = 0.f, s2 = 0.f;
        #pragma unroll
        for (int j = 0; j < 8; j++) {
            float v = tile[r * 257 + lane + j * 32];
            s += v; s2 += v * v;
        }
        #pragma unroll
        for (int o = 16; o; o >>= 1) {
            s  += __shfl_xor_sync(0xffffffffu, s, o);
            s2 += __shfl_xor_sync(0xffffffffu, s2, o);
        }
        if (lane == 0) {
            float mu = s * (1.0f / 256.0f);
            smu[r] = mu;
            srs[r] = rsqrtf(s2 * (1.0f / 256.0f) - mu * mu + 1e-5f);
        }
    }
    __syncthreads();

    #pragma unroll
    for (int l = t; l < 32 * DD; l += 256) {
        int d = l >> 5, i = l & 31;   // d warp-uniform, i = lane
        float v = (tile[i * 257 + d] - smu[i]) * srs[i] * gamma[d] + beta[d];
        g_xh[((long)b * DD + d) * NN + n0 + i] = v;
        tile[i * 257 + d] = v;
    }
    __syncthreads();

    {
        float s = 0.f;
        #pragma unroll
        for (int i = 0; i < 32; i++) s += tile[i * 257 + t];
        atomicAdd(&g_ctx[b * DD + t], s);
    }
}

// ---------------- MLP layer 1 (8-way split-K, 512 thr) -> hmidT ----------------
__global__ __launch_bounds__(512) void mlp1_kernel(const float* __restrict__ W1,
                                                   const float* __restrict__ b1) {
    __shared__ float sc[DD];
    __shared__ float part[8][64];
    int b = blockIdx.x, o0 = blockIdx.y * 64;
    int t = threadIdx.x;
    if (t < DD) sc[t] = g_ctx[b * DD + t] * (1.0f / NN);
    __syncthreads();
    int ol = t & 63, kp = t >> 6;
    int o = o0 + ol;
    float acc = 0.f;
    #pragma unroll 8
    for (int d = kp * 32; d < kp * 32 + 32; d++) acc += sc[d] * W1[d * DD + o];
    part[kp][ol] = acc;
    __syncthreads();
    if (t < 64) {
        float a = b1[o0 + t];
        #pragma unroll
        for (int p = 0; p < 8; p++) a += part[p][t];
        g_hmidT[(o0 + t) * BB + b] = 0.5f * a * (1.0f + erff(a * 0.70710678118654752f));
    }
}

// ---------------- MLP layer 2 (batched over b, 4-way split-K, 1024 thr, dyn smem) ----------------
__global__ __launch_bounds__(1024) void mlp2_kernel(const float* __restrict__ W2,
                                                    const float* __restrict__ b2,
                                                    const float* __restrict__ base_filter,
                                                    const float* __restrict__ base_bias) {
    extern __shared__ float dynsm[];
    float* sh   = dynsm;                 // hmidT copy: [j][b]   (32 KB)
    float* part = dynsm + DD * BB;       // partials for kp=1..3 (24 KB)
    int t = threadIdx.x;
    #pragma unroll
    for (int i = t; i < DD * BB; i += 1024) sh[i] = g_hmidT[i];
    __syncthreads();

    int ol = t & 63, bg = (t >> 6) & 3, kp = t >> 8;
    int o = blockIdx.x * 64 + ol;
    bool valid = (o < OUT2);
    int b0 = bg * 8;

    u64 acc0 = 0, acc1 = 0, acc2 = 0, acc3 = 0;
    if (valid) {
        #pragma unroll 4
        for (int j = kp * 64; j < kp * 64 + 64; j++) {
            float wv = W2[(long)j * OUT2 + o];
            u64 wp = pk2(wv, wv);
            const ulonglong2* hp = (const ulonglong2*)&sh[j * BB + b0];
            ulonglong2 p0 = hp[0], p1 = hp[1];
            acc0 = f2fma(p0.x, wp, acc0);
            acc1 = f2fma(p0.y, wp, acc1);
            acc2 = f2fma(p1.x, wp, acc2);
            acc3 = f2fma(p1.y, wp, acc3);
        }
    }
    if (kp > 0) {
        u64* pp = (u64*)&part[((kp - 1) * 256 + (t & 255)) * 8];
        pp[0] = acc0; pp[1] = acc1; pp[2] = acc2; pp[3] = acc3;
    }
    __syncthreads();
    if (kp == 0 && valid) {
        #pragma unroll
        for (int p = 0; p < 3; p++) {
            const u64* pp = (const u64*)&part[(p * 256 + (t & 255)) * 8];
            acc0 = add2(acc0, pp[0]);
            acc1 = add2(acc1, pp[1]);
            acc2 = add2(acc2, pp[2]);
            acc3 = add2(acc3, pp[3]);
        }
        float a[8];
        upk2(acc0, a[0], a[1]); upk2(acc1, a[2], a[3]);
        upk2(acc2, a[4], a[5]); upk2(acc3, a[6], a[7]);
        float bias2 = b2[o];
        int idx2 = o >> 1;
        if ((o & 1) == 0) {
            float base = base_filter[idx2];
            #pragma unroll
            for (int r = 0; r < 8; r++)
                g_filt[(long)(b0 + r) * HF + idx2] = base * (1.0f + a[r] + bias2);
        } else {
            float base = base_bias[idx2];
            #pragma unroll
            for (int r = 0; r < 8; r++)
                g_bias[(long)(b0 + r) * HF + idx2] = base + a[r] + bias2;
        }
    }
}

// ---------------- spectral kernel: complex packing + tap-interleaved smem ----
// 288 threads: e = t%12, g = t/12 (col pair c2=2g, 2g+1). Radix-4, f32x2.
// All inter-stage arrays stored via L2i: 4 taps x 2 cols = 8 contiguous floats.
__global__ __launch_bounds__(288) void spectral_kernel() {
    __shared__ float sm[120 + 4 * 2496];
    float2* w12 = (float2*)sm;             // 12 entries
    float2* w48 = (float2*)(sm + 24);      // 48 entries
    float*  bufA = sm + 120;               // re plane
    float*  Xim  = bufA + 2496;            // im plane
    float*  wre  = Xim + 2496;
    float*  wim  = wre + 2496;

    int blk = blockIdx.x;                  // 4096 = BB * 128
    int b = blk >> 7;
    int d0 = (blk & 127) * 2;
    int h = d0 >> 5;
    int t = threadIdx.x;
    int e  = t % 12;
    int gq = t / 12;                       // col-pair index
    int c2 = gq * 2;
    const float inv48 = 1.0f / 48.0f;
    const u64 NEG1 = pk2(-1.0f, -1.0f);
    int rowg = c2 >> 2;                    // for stage1/3 writes
    int qoff = (c2 & 3) << 1;

    if (t < 12) w12[t] = g_tw[192 * t];
    else if (t < 60) w48[t - 12] = g_tw[48 * (t - 12)];
    const float* srcA = g_xh + ((long)b * DD + d0) * NN;
    const float* srcB = srcA + NN;
    for (int i = t; i < NN; i += 288) {
        int n1 = i / 48, n2 = i - n1 * 48;
        int li = L2i(n1, n2);
        bufA[li] = srcA[i]; Xim[li] = srcB[i];
    }
    __syncthreads();

    float2 we1 = w48[e], we2 = w48[2 * e], we3 = w48[3 * e];
    u64 c1=pk2(we1.x,we1.x), s1=pk2(we1.y,we1.y), n1b=pk2(-we1.y,-we1.y);
    u64 c2p=pk2(we2.x,we2.x), s2p=pk2(we2.y,we2.y), n2p=pk2(-we2.y,-we2.y);
    u64 c3=pk2(we3.x,we3.x), s3=pk2(we3.y,we3.y), n3=pk2(-we3.y,-we3.y);

    // ======== stage 1: forward over n1 (complex input); out -> wre/wim L2(n2,k) ========
    {
        u64 S0r=0,S0i=0,S1r=0,S1i=0,S2r=0,S2i=0,S3r=0,S3i=0;
        int idx = 0;
        #pragma unroll
        for (int m = 0; m < 12; m++) {
            float2 w = w12[idx]; idx += e; if (idx >= 12) idx -= 12;
            u64 cc = pk2(w.x, w.x), ss = pk2(w.y, w.y), ns = pk2(-w.y, -w.y);
            const ulonglong2* pr = (const ulonglong2*)&bufA[(m * 26 + gq) * 8];
            const ulonglong2* pi = (const ulonglong2*)&Xim [(m * 26 + gq) * 8];
            ulonglong2 r01 = pr[0], r23 = pr[1];
            ulonglong2 i01 = pi[0], i23 = pi[1];
            S0r = f2fma(r01.x, cc, S0r); S0r = f2fma(i01.x, ss, S0r);
            S0i = f2fma(i01.x, cc, S0i); S0i = f2fma(r01.x, ns, S0i);
            S1r = f2fma(r01.y, cc, S1r); S1r = f2fma(i01.y, ss, S1r);
            S1i = f2fma(i01.y, cc, S1i); S1i = f2fma(r01.y, ns, S1i);
            S2r = f2fma(r23.x, cc, S2r); S2r = f2fma(i23.x, ss, S2r);
            S2i = f2fma(i23.x, cc, S2i); S2i = f2fma(r23.x, ns, S2i);
            S3r = f2fma(r23.y, cc, S3r); S3r = f2fma(i23.y, ss, S3r);
            S3i = f2fma(i23.y, cc, S3i); S3i = f2fma(r23.y, ns, S3i);
        }
        u64 T1r = f2fma(S1i, s1, mul2(S1r, c1)),  T1i = f2fma(S1r, n1b, mul2(S1i, c1));
        u64 T2r = f2fma(S2i, s2p, mul2(S2r, c2p)), T2i = f2fma(S2r, n2p, mul2(S2i, c2p));
        u64 T3r = f2fma(S3i, s3, mul2(S3r, c3)),  T3i = f2fma(S3r, n3, mul2(S3i, c3));
        u64 ar = add2(S0r, T2r), ai = add2(S0i, T2i);
        u64 br = f2fma(T2r, NEG1, S0r), bi = f2fma(T2i, NEG1, S0i);
        u64 cr = add2(T1r, T3r), ci = add2(T1i, T3i);
        u64 dr = f2fma(T3r, NEG1, T1r), di = f2fma(T3i, NEG1, T1i);
        u64 Xr[4], Xi4[4];
        Xr[0] = add2(ar, cr);          Xi4[0] = add2(ai, ci);
        Xr[1] = add2(br, di);          Xi4[1] = f2fma(dr, NEG1, bi);
        Xr[2] = f2fma(cr, NEG1, ar);   Xi4[2] = f2fma(ci, NEG1, ai);
        Xr[3] = f2fma(di, NEG1, br);   Xi4[3] = add2(bi, dr);
        #pragma unroll
        for (int p = 0; p < 4; p++) {
            float r0, r1, i0, i1;
            upk2(Xr[p], r0, r1); upk2(Xi4[p], i0, i1);
            int k = e + 12 * p;
            int base = ((rowg * 26 + (k >> 1)) << 3) + (k & 1) + qoff;
            float2 ta = g_tw[k * c2];
            wre[base]     = r0 * ta.x + i0 * ta.y;
            wim[base]     = i0 * ta.x - r0 * ta.y;
            float2 tb = g_tw[k * (c2 + 1)];
            wre[base + 2] = r1 * tb.x + i1 * tb.y;
            wim[base + 2] = i1 * tb.x - r1 * tb.y;
        }
    }
    __syncthreads();

    // ======== stage 2: forward over n2; out raw Z -> bufA/Xim L2(k2,k1) ========
    {
        u64 S0r=0,S0i=0,S1r=0,S1i=0,S2r=0,S2i=0,S3r=0,S3i=0;
        int idx = 0;
        #pragma unroll
        for (int m = 0; m < 12; m++) {
            float2 w = w12[idx]; idx += e; if (idx >= 12) idx -= 12;
            u64 cc = pk2(w.x, w.x), ss = pk2(w.y, w.y), ns = pk2(-w.y, -w.y);
            const ulonglong2* pr = (const ulonglong2*)&wre[(m * 26 + gq) * 8];
            const ulonglong2* pi = (const ulonglong2*)&wim[(m * 26 + gq) * 8];
            ulonglong2 r01 = pr[0], r23 = pr[1];
            ulonglong2 i01 = pi[0], i23 = pi[1];
            S0r = f2fma(r01.x, cc, S0r); S0r = f2fma(i01.x, ss, S0r);
            S0i = f2fma(i01.x, cc, S0i); S0i = f2fma(r01.x, ns, S0i);
            S1r = f2fma(r01.y, cc, S1r); S1r = f2fma(i01.y, ss, S1r);
            S1i = f2fma(i01.y, cc, S1i); S1i = f2fma(r01.y, ns, S1i);
            S2r = f2fma(r23.x, cc, S2r); S2r = f2fma(i23.x, ss, S2r);
            S2i = f2fma(i23.x, cc, S2i); S2i = f2fma(r23.x, ns, S2i);
            S3r = f2fma(r23.y, cc, S3r); S3r = f2fma(i23.y, ss, S3r);
            S3i = f2fma(i23.y, cc, S3i); S3i = f2fma(r23.y, ns, S3i);
        }
        u64 T1r = f2fma(S1i, s1, mul2(S1r, c1)),  T1i = f2fma(S1r, n1b, mul2(S1i, c1));
        u64 T2r = f2fma(S2i, s2p, mul2(S2r, c2p)), T2i = f2fma(S2r, n2p, mul2(S2i, c2p));
        u64 T3r = f2fma(S3i, s3, mul2(S3r, c3)),  T3i = f2fma(S3r, n3, mul2(S3i, c3));
        u64 ar = add2(S0r, T2r), ai = add2(S0i, T2i);
        u64 br = f2fma(T2r, NEG1, S0r), bi = f2fma(T2i, NEG1, S0i);
        u64 cr = add2(T1r, T3r), ci = add2(T1i, T3i);
        u64 dr = f2fma(T3r, NEG1, T1r), di = f2fma(T3i, NEG1, T1i);
        u64 Zr[4], Zi[4];
        Zr[0] = add2(ar, cr);          Zi[0] = add2(ai, ci);
        Zr[1] = add2(br, di);          Zi[1] = f2fma(dr, NEG1, bi);
        Zr[2] = f2fma(cr, NEG1, ar);   Zi[2] = f2fma(ci, NEG1, ai);
        Zr[3] = f2fma(di, NEG1, br);   Zi[3] = add2(bi, dr);
        #pragma unroll
        for (int p = 0; p < 4; p++) {
            int k2 = e + 12 * p;
            int base = (((k2 >> 2) * 26 + gq) << 3) + ((k2 & 3) << 1);
            *(u64*)&bufA[base] = Zr[p];
            *(u64*)&Xim [base] = Zi[p];
        }
    }
    __syncthreads();

    // ======== mid-pass: Hermitian split, modulate (k <= 1152), repack ========
    {
        const float* fB = g_filt + (long)b * HF + (long)h * FB;
        const float* cB = g_bias + (long)b * HF + (long)h * FB;
        const float sc = 0.5f * inv48;
        for (int k = t; k <= 1152; k += 288) {
            int a = k / 48, bq = k - a * 48;
            int a2, b2q;
            if (bq == 0) { a2 = (48 - a) % 48; b2q = 0; }
            else         { a2 = 47 - a;        b2q = 48 - bq; }
            int i1 = L2i(a, bq), i2 = L2i(a2, b2q);
            float Zr = bufA[i1], Zi = Xim[i1];
            float Mr = bufA[i2], Mi = Xim[i2];
            float Ar = (Zr + Mr) * sc, Ai = (Zi - Mi) * sc;
            float Br = (Zi + Mi) * sc, Bi = (Mr - Zr) * sc;
            float g = fB[k], cc = cB[k];
            float mr = Ar * g + cc, mi = Ai * g;
            float mag = sqrtf(mr * mr + mi * mi);
            float fac = 0.5f * mag * (1.0f + erff(mag * 0.70710678118654752f))
                        * __fdividef(1.0f, mag + 1e-6f);
            float TAr = mr * fac, TAi = mi * fac;
            mr = Br * g + cc; mi = Bi * g;
            mag = sqrtf(mr * mr + mi * mi);
            fac = 0.5f * mag * (1.0f + erff(mag * 0.70710678118654752f))
                  * __fdividef(1.0f, mag + 1e-6f);
            float TBr = mr * fac, TBi = mi * fac;
            bufA[i1] = TAr - TBi;  Xim[i1] = TAi + TBr;
            bufA[i2] = TAr + TBi;  Xim[i2] = TBr - TAi;
        }
    }
    __syncthreads();

    // ======== stage 3: inverse over k2; out -> wre/wim L2(k1,r) ========
    {
        u64 S0r=0,S0i=0,S1r=0,S1i=0,S2r=0,S2i=0,S3r=0,S3i=0;
        int idx = 0;
        #pragma unroll
        for (int m = 0; m < 12; m++) {
            float2 w = w12[idx]; idx += e; if (idx >= 12) idx -= 12;
            u64 cc = pk2(w.x, w.x), ss = pk2(w.y, w.y), ns = pk2(-w.y, -w.y);
            const ulonglong2* pr = (const ulonglong2*)&bufA[(m * 26 + gq) * 8];
            const ulonglong2* pi = (const ulonglong2*)&Xim [(m * 26 + gq) * 8];
            ulonglong2 r01 = pr[0], r23 = pr[1];
            ulonglong2 i01 = pi[0], i23 = pi[1];
            S0r = f2fma(r01.x, cc, S0r); S0r = f2fma(i01.x, ns, S0r);
            S0i = f2fma(i01.x, cc, S0i); S0i = f2fma(r01.x, ss, S0i);
            S1r = f2fma(r01.y, cc, S1r); S1r = f2fma(i01.y, ns, S1r);
            S1i = f2fma(i01.y, cc, S1i); S1i = f2fma(r01.y, ss, S1i);
            S2r = f2fma(r23.x, cc, S2r); S2r = f2fma(i23.x, ns, S2r);
            S2i = f2fma(i23.x, cc, S2i); S2i = f2fma(r23.x, ss, S2i);
            S3r = f2fma(r23.y, cc, S3r); S3r = f2fma(i23.y, ns, S3r);
            S3i = f2fma(i23.y, cc, S3i); S3i = f2fma(r23.y, ss, S3i);
        }
        u64 T1r = f2fma(S1i, n1b, mul2(S1r, c1)),  T1i = f2fma(S1r, s1, mul2(S1i, c1));
        u64 T2r = f2fma(S2i, n2p, mul2(S2r, c2p)), T2i = f2fma(S2r, s2p, mul2(S2i, c2p));
        u64 T3r = f2fma(S3i, n3, mul2(S3r, c3)),  T3i = f2fma(S3r, s3, mul2(S3i, c3));
        u64 ar = add2(S0r, T2r), ai = add2(S0i, T2i);
        u64 br = f2fma(T2r, NEG1, S0r), bi = f2fma(T2i, NEG1, S0i);
        u64 cr = add2(T1r, T3r), ci = add2(T1i, T3i);
        u64 dr = f2fma(T3r, NEG1, T1r), di = f2fma(T3i, NEG1, T1i);
        u64 Xr[4], Xi4[4];
        Xr[0] = add2(ar, cr);          Xi4[0] = add2(ai, ci);
        Xr[1] = f2fma(di, NEG1, br);   Xi4[1] = add2(bi, dr);          // b + i d
        Xr[2] = f2fma(cr, NEG1, ar);   Xi4[2] = f2fma(ci, NEG1, ai);
        Xr[3] = add2(br, di);          Xi4[3] = f2fma(dr, NEG1, bi);   // b - i d
        #pragma unroll
        for (int p = 0; p < 4; p++) {
            float r0, r1, i0, i1;
            upk2(Xr[p], r0, r1); upk2(Xi4[p], i0, i1);
            int r = e + 12 * p;
            int base = ((rowg * 26 + (r >> 1)) << 3) + (r & 1) + qoff;
            float2 ta = g_tw[r * c2];
            wre[base]     = r0 * ta.x - i0 * ta.y;
            wim[base]     = r0 * ta.y + i0 * ta.x;
            float2 tb = g_tw[r * (c2 + 1)];
            wre[base + 2] = r1 * tb.x - i1 * tb.y;
            wim[base + 2] = r1 * tb.y + i1 * tb.x;
        }
    }
    __syncthreads();

    // ======== stage 4: inverse over k1 (full complex out: re->colA, im->colB) ========
    {
        u64 S0r=0,S0i=0,S1r=0,S1i=0,S2r=0,S2i=0,S3r=0,S3i=0;
        int idx = 0;
        #pragma unroll
        for (int m = 0; m < 12; m++) {
            float2 w = w12[idx]; idx += e; if (idx >= 12) idx -= 12;
            u64 cc = pk2(w.x, w.x), ss = pk2(w.y, w.y), ns = pk2(-w.y, -w.y);
            const ulonglong2* pr = (const ulonglong2*)&wre[(m * 26 + gq) * 8];
            const ulonglong2* pi = (const ulonglong2*)&wim[(m * 26 + gq) * 8];
            ulonglong2 r01 = pr[0], r23 = pr[1];
            ulonglong2 i01 = pi[0], i23 = pi[1];
            S0r = f2fma(r01.x, cc, S0r); S0r = f2fma(i01.x, ns, S0r);
            S0i = f2fma(i01.x, cc, S0i); S0i = f2fma(r01.x, ss, S0i);
            S1r = f2fma(r01.y, cc, S1r); S1r = f2fma(i01.y, ns, S1r);
            S1i = f2fma(i01.y, cc, S1i); S1i = f2fma(r01.y, ss, S1i);
            S2r = f2fma(r23.x, cc, S2r); S2r = f2fma(i23.x, ns, S2r);
            S2i = f2fma(i23.x, cc, S2i); S2i = f2fma(r23.x, ss, S2i);
            S3r = f2fma(r23.y, cc, S3r); S3r = f2fma(i23.y, ns, S3r);
            S3i = f2fma(i23.y, cc, S3i); S3i = f2fma(r23.y, ss, S3i);
        }
        u64 T1r = f2fma(S1i, n1b, mul2(S1r, c1)),  T1i = f2fma(S1r, s1, mul2(S1i, c1));
        u64 T2r = f2fma(S2i, n2p, mul2(S2r, c2p)), T2i = f2fma(S2r, s2p, mul2(S2i, c2p));
        u64 T3r = f2fma(S3i, n3, mul2(S3r, c3)),  T3i = f2fma(S3r, s3, mul2(S3i, c3));
        u64 ar = add2(S0r, T2r), ai = add2(S0i, T2i);
        u64 br = f2fma(T2r, NEG1, S0r), bi = f2fma(T2i, NEG1, S0i);
        u64 cr = add2(T1r, T3r), ci = add2(T1i, T3i);
        u64 dr = f2fma(T3r, NEG1, T1r), di = f2fma(T3i, NEG1, T1i);
        u64 I48 = pk2(inv48, inv48);
        float* dstA = g_yt + ((long)b * DD + d0) * NN;
        float* dstB = dstA + NN;
        u64 Xr, Xi;
        Xr = add2(ar, cr);          Xi = add2(ai, ci);
        *(u64*)&dstA[(e     ) * 48 + c2] = mul2(Xr, I48);
        *(u64*)&dstB[(e     ) * 48 + c2] = mul2(Xi, I48);
        Xr = f2fma(di, NEG1, br);   Xi = add2(bi, dr);
        *(u64*)&dstA[(e + 12) * 48 + c2] = mul2(Xr, I48);
        *(u64*)&dstB[(e + 12) * 48 + c2] = mul2(Xi, I48);
        Xr = f2fma(cr, NEG1, ar);   Xi = f2fma(ci, NEG1, ai);
        *(u64*)&dstA[(e + 24) * 48 + c2] = mul2(Xr, I48);
        *(u64*)&dstB[(e + 24) * 48 + c2] = mul2(Xi, I48);
        Xr = add2(br, di);          Xi = f2fma(dr, NEG1, bi);
        *(u64*)&dstA[(e + 36) * 48 + c2] = mul2(Xr, I48);
        *(u64*)&dstB[(e + 36) * 48 + c2] = mul2(Xi, I48);
    }
}

// ---------------- output: out[b][n][d] = x + yt^T ----------------
__global__ void addout_kernel(const float* __restrict__ x, float* __restrict__ out) {
    __shared__ float tile[32][33];
    int b  = blockIdx.z;
    int n0 = blockIdx.x * 32;
    int d0 = blockIdx.y * 32;
    int tx = threadIdx.x, ty = threadIdx.y;
    const float* src = g_yt + ((long)b * DD + d0) * NN + n0;
    #pragma unroll
    for (int i = 0; i < 32; i += 8)
        tile[ty + i][tx] = src[(long)(ty + i) * NN + tx];
    __syncthreads();
    long base = ((long)b * NN + n0) * DD + d0;
    #pragma unroll
    for (int i = 0; i < 32; i += 8)
        out[base + (long)(ty + i) * DD + tx] =
            x[base + (long)(ty + i) * DD + tx] + tile[tx][ty + i];
}

// ---------------- launch ----------------
extern "C" void kernel_launch(void* const* d_in, const int* in_sizes, int n_in,
                              void* d_out, int out_size) {
    const float* x           = (const float*)d_in[0];
    const float* base_filter = (const float*)d_in[1];
    const float* base_bias   = (const float*)d_in[2];
    const float* ln_gamma    = (const float*)d_in[3];
    const float* ln_beta     = (const float*)d_in[4];
    const float* W1          = (const float*)d_in[5];
    const float* b1          = (const float*)d_in[6];
    const float* W2          = (const float*)d_in[7];
    const float* b2          = (const float*)d_in[8];
    float* out = (float*)d_out;

    static bool attr_done = false;
    if (!attr_done) {
        cudaFuncSetAttribute(mlp2_kernel,
                             cudaFuncAttributeMaxDynamicSharedMemorySize, MLP2_SMEM);
        attr_done = true;
    }

    init_kernel<<<32, 256>>>();
    ln_t_kernel<<<dim3(NN / 32, BB), 256>>>(x, ln_gamma, ln_beta);
    mlp1_kernel<<<dim3(BB, 4), 512>>>(W1, b1);
    mlp2_kernel<<<(OUT2 + 63) / 64, 1024, MLP2_SMEM>>>(W2, b2, base_filter, base_bias);
    spectral_kernel<<<BB * DD / 2, 288>>>();
    addout_kernel<<<dim3(NN / 32, DD / 32, BB), dim3(32, 8)>>>(x, out);
}

// round 15
// speedup vs baseline: 1.0466x; 1.0466x over previous
#include <cuda_runtime.h>
#include <cuda_bf16.h>

// Problem constants
#define BB   32
#define DD   256
#define NN   2304      // 48*48
#define HEADS 8
#define FB   1153      // NN/2+1
#define HF   (HEADS*FB)        // 9224
#define OUT2 (HEADS*FB*2)      // 18448

#define MLP2_SMEM ((DD*BB + 3*256*8) * 4)   // 57344 bytes

// ---------------- scratch ----------------
__device__ float  g_xh   [BB*DD*NN];   // [b][d][n]
__device__ float  g_yt   [BB*DD*NN];   // filtered, [b][d][n]
__device__ float  g_ctx  [BB*DD];      // raw sums (atomic), scaled in mlp1
__device__ float  g_hmidT[DD*BB];      // transposed: [o][b]
__device__ float  g_filt [BB*HF];
__device__ float  g_bias [BB*HF];
__device__ float2 g_tw   [NN];         // (cos, sin)(2*pi*j/2304)

typedef unsigned long long u64;

// ---------------- packed f32x2 helpers ----------------
__device__ __forceinline__ u64 pk2(float lo, float hi) {
    u64 r; asm("mov.b64 %0, {%1,%2};" : "=l"(r) : "f"(lo), "f"(hi)); return r;
}
__device__ __forceinline__ void upk2(u64 v, float& lo, float& hi) {
    asm("mov.b64 {%0,%1}, %2;" : "=f"(lo), "=f"(hi) : "l"(v));
}
__device__ __forceinline__ u64 f2fma(u64 a, u64 b, u64 c) {
    u64 d; asm("fma.rn.f32x2 %0, %1, %2, %3;" : "=l"(d) : "l"(a), "l"(b), "l"(c)); return d;
}
__device__ __forceinline__ u64 add2(u64 a, u64 b) {
    u64 d; asm("add.rn.f32x2 %0, %1, %2;" : "=l"(d) : "l"(a), "l"(b)); return d;
}
__device__ __forceinline__ u64 mul2(u64 a, u64 b) {
    u64 d; asm("mul.rn.f32x2 %0, %1, %2;" : "=l"(d) : "l"(a), "l"(b)); return d;
}

// ---------------- init: twiddles + zero ctx ----------------
__global__ void init_kernel() {
    int j = blockIdx.x * blockDim.x + threadIdx.x;   // 8192 threads
    if (j < NN) {
        float sv, cv;
        sincospif((float)j * (1.0f / 1152.0f), &sv, &cv);
        g_tw[j] = make_float2(cv, sv);
    }
    g_ctx[j] = 0.f;
}

// ---------------- fused LayerNorm + transpose + ctx partials ----------------
__global__ __launch_bounds__(256) void ln_t_kernel(const float* __restrict__ x,
                                                   const float* __restrict__ gamma,
                                                   const float* __restrict__ beta) {
    __shared__ float tile[32 * 257];
    __shared__ float smu[32], srs[32];
    int b  = blockIdx.y;
    int n0 = blockIdx.x * 32;
    int t  = threadIdx.x;

    const float* src = x + ((long)b * NN + n0) * DD;
    #pragma unroll
    for (int l = t; l < 32 * DD; l += 256) {
        int r = l >> 8, d = l & 255;
        tile[r * 257 + d] = src[l];
    }
    __syncthreads();

    int w = t >> 5, lane = t & 31;
    #pragma unroll
    for (int r = w; r < 32; r += 8) {
        float s = 0.f, s2 = 0.f;
        #pragma unroll
        for (int j = 0; j < 8; j++) {
            float v = tile[r * 257 + lane + j * 32];
            s += v; s2 += v * v;
        }
        #pragma unroll
        for (int o = 16; o; o >>= 1) {
            s  += __shfl_xor_sync(0xffffffffu, s, o);
            s2 += __shfl_xor_sync(0xffffffffu, s2, o);
        }
        if (lane == 0) {
            float mu = s * (1.0f / 256.0f);
            smu[r] = mu;
            srs[r] = rsqrtf(s2 * (1.0f / 256.0f) - mu * mu + 1e-5f);
        }
    }
    __syncthreads();

    // normalize: write transposed to gmem AND back into tile (for ctx pass)
    #pragma unroll
    for (int l = t; l < 32 * DD; l += 256) {
        int d = l >> 5, i = l & 31;   // d warp-uniform, i = lane
        float v = (tile[i * 257 + d] - smu[i]) * srs[i] * gamma[d] + beta[d];
        g_xh[((long)b * DD + d) * NN + n0 + i] = v;
        tile[i * 257 + d] = v;
    }
    __syncthreads();

    // ctx partials: thread t = d, sum 32 rows, single atomic
    {
        float s = 0.f;
        #pragma unroll
        for (int i = 0; i < 32; i++) s += tile[i * 257 + t];
        atomicAdd(&g_ctx[b * DD + t], s);
    }
}

// ---------------- MLP layer 1 (8-way split-K, 512 thr) -> hmidT ----------------
__global__ __launch_bounds__(512) void mlp1_kernel(const float* __restrict__ W1,
                                                   const float* __restrict__ b1) {
    __shared__ float sc[DD];
    __shared__ float part[8][64];
    int b = blockIdx.x, o0 = blockIdx.y * 64;
    int t = threadIdx.x;
    if (t < DD) sc[t] = g_ctx[b * DD + t] * (1.0f / NN);
    __syncthreads();
    int ol = t & 63, kp = t >> 6;     // kp 0..7
    int o = o0 + ol;
    float acc = 0.f;
    #pragma unroll 8
    for (int d = kp * 32; d < kp * 32 + 32; d++) acc += sc[d] * W1[d * DD + o];
    part[kp][ol] = acc;
    __syncthreads();
    if (t < 64) {
        float a = b1[o0 + t];
        #pragma unroll
        for (int p = 0; p < 8; p++) a += part[p][t];
        g_hmidT[(o0 + t) * BB + b] = 0.5f * a * (1.0f + erff(a * 0.70710678118654752f));
    }
}

// ---------------- MLP layer 2 (batched over b, 4-way split-K, 1024 thr, dyn smem) ----------------
__global__ __launch_bounds__(1024) void mlp2_kernel(const float* __restrict__ W2,
                                                    const float* __restrict__ b2,
                                                    const float* __restrict__ base_filter,
                                                    const float* __restrict__ base_bias) {
    extern __shared__ float dynsm[];
    float* sh   = dynsm;                 // hmidT copy: [j][b]   (32 KB)
    float* part = dynsm + DD * BB;       // partials for kp=1..3 (24 KB)
    int t = threadIdx.x;
    #pragma unroll
    for (int i = t; i < DD * BB; i += 1024) sh[i] = g_hmidT[i];
    __syncthreads();

    int ol = t & 63, bg = (t >> 6) & 3, kp = t >> 8;   // kp 0..3
    int o = blockIdx.x * 64 + ol;
    bool valid = (o < OUT2);
    int b0 = bg * 8;

    u64 acc0 = 0, acc1 = 0, acc2 = 0, acc3 = 0;
    if (valid) {
        #pragma unroll 4
        for (int j = kp * 64; j < kp * 64 + 64; j++) {
            float wv = W2[(long)j * OUT2 + o];
            u64 wp = pk2(wv, wv);
            const ulonglong2* hp = (const ulonglong2*)&sh[j * BB + b0];
            ulonglong2 p0 = hp[0], p1 = hp[1];
            acc0 = f2fma(p0.x, wp, acc0);
            acc1 = f2fma(p0.y, wp, acc1);
            acc2 = f2fma(p1.x, wp, acc2);
            acc3 = f2fma(p1.y, wp, acc3);
        }
    }
    if (kp > 0) {
        u64* pp = (u64*)&part[((kp - 1) * 256 + (t & 255)) * 8];
        pp[0] = acc0; pp[1] = acc1; pp[2] = acc2; pp[3] = acc3;
    }
    __syncthreads();
    if (kp == 0 && valid) {
        #pragma unroll
        for (int p = 0; p < 3; p++) {
            const u64* pp = (const u64*)&part[(p * 256 + (t & 255)) * 8];
            acc0 = add2(acc0, pp[0]);
            acc1 = add2(acc1, pp[1]);
            acc2 = add2(acc2, pp[2]);
            acc3 = add2(acc3, pp[3]);
        }
        float a[8];
        upk2(acc0, a[0], a[1]); upk2(acc1, a[2], a[3]);
        upk2(acc2, a[4], a[5]); upk2(acc3, a[6], a[7]);
        float bias2 = b2[o];
        int idx2 = o >> 1;
        if ((o & 1) == 0) {
            float base = base_filter[idx2];
            #pragma unroll
            for (int r = 0; r < 8; r++)
                g_filt[(long)(b0 + r) * HF + idx2] = base * (1.0f + a[r] + bias2);
        } else {
            float base = base_bias[idx2];
            #pragma unroll
            for (int r = 0; r < 8; r++)
                g_bias[(long)(b0 + r) * HF + idx2] = base + a[r] + bias2;
        }
    }
}

// ---------------- spectral kernel: 2 real columns per block via complex packing ----
// z = x_a + i x_b (d-pair shares head h -> same filter). Radix-4 (48 = 4x12), f32x2.
// 288 threads: e = t%12, c2 = (t/12)*2.
__global__ __launch_bounds__(288) void spectral_kernel() {
    __shared__ float sm[120 + 4 * 2496];
    float2* w12 = (float2*)sm;             // 12 entries
    float2* w48 = (float2*)(sm + 24);      // 48 entries
    float*  bufA = sm + 120;               // re plane (stride 48 -> 52)
    float*  Xim  = bufA + 2496;            // im plane
    float*  wre  = Xim + 2496;
    float*  wim  = wre + 2496;

    int blk = blockIdx.x;                  // 4096 = BB * 128
    int b = blk >> 7;
    int d0 = (blk & 127) * 2;
    int h = d0 >> 5;
    int t = threadIdx.x;
    int e  = t % 12;
    int c2 = (t / 12) * 2;
    const float inv48 = 1.0f / 48.0f;
    const u64 NEG1 = pk2(-1.0f, -1.0f);

    if (t < 12) w12[t] = g_tw[192 * t];
    else if (t < 60) w48[t - 12] = g_tw[48 * (t - 12)];
    const float* srcA = g_xh + ((long)b * DD + d0) * NN;
    const float* srcB = srcA + NN;
    for (int i = t; i < NN; i += 288) { bufA[i] = srcA[i]; Xim[i] = srcB[i]; }
    __syncthreads();

    float2 we1 = w48[e], we2 = w48[2 * e], we3 = w48[3 * e];
    u64 c1=pk2(we1.x,we1.x), s1=pk2(we1.y,we1.y), n1=pk2(-we1.y,-we1.y);
    u64 c2p=pk2(we2.x,we2.x), s2p=pk2(we2.y,we2.y), n2p=pk2(-we2.y,-we2.y);
    u64 c3=pk2(we3.x,we3.x), s3=pk2(we3.y,we3.y), n3=pk2(-we3.y,-we3.y);

    // ======== stage 1: forward over n1 (complex input), rows stride 48 ========
    {
        u64 S0r=0,S0i=0,S1r=0,S1i=0,S2r=0,S2i=0,S3r=0,S3i=0;
        int idx = 0;
        #pragma unroll
        for (int m = 0; m < 12; m++) {
            float2 w = w12[idx]; idx += e; if (idx >= 12) idx -= 12;
            u64 cc = pk2(w.x, w.x), ss = pk2(w.y, w.y), ns = pk2(-w.y, -w.y);
            u64 vr0 = *(const u64*)&bufA[(4*m+0)*48 + c2], vi0 = *(const u64*)&Xim[(4*m+0)*48 + c2];
            u64 vr1 = *(const u64*)&bufA[(4*m+1)*48 + c2], vi1 = *(const u64*)&Xim[(4*m+1)*48 + c2];
            u64 vr2 = *(const u64*)&bufA[(4*m+2)*48 + c2], vi2 = *(const u64*)&Xim[(4*m+2)*48 + c2];
            u64 vr3 = *(const u64*)&bufA[(4*m+3)*48 + c2], vi3 = *(const u64*)&Xim[(4*m+3)*48 + c2];
            S0r = f2fma(vr0, cc, S0r); S0r = f2fma(vi0, ss, S0r);
            S0i = f2fma(vi0, cc, S0i); S0i = f2fma(vr0, ns, S0i);
            S1r = f2fma(vr1, cc, S1r); S1r = f2fma(vi1, ss, S1r);
            S1i = f2fma(vi1, cc, S1i); S1i = f2fma(vr1, ns, S1i);
            S2r = f2fma(vr2, cc, S2r); S2r = f2fma(vi2, ss, S2r);
            S2i = f2fma(vi2, cc, S2i); S2i = f2fma(vr2, ns, S2i);
            S3r = f2fma(vr3, cc, S3r); S3r = f2fma(vi3, ss, S3r);
            S3i = f2fma(vi3, cc, S3i); S3i = f2fma(vr3, ns, S3i);
        }
        u64 T1r = f2fma(S1i, s1, mul2(S1r, c1)),  T1i = f2fma(S1r, n1, mul2(S1i, c1));
        u64 T2r = f2fma(S2i, s2p, mul2(S2r, c2p)), T2i = f2fma(S2r, n2p, mul2(S2i, c2p));
        u64 T3r = f2fma(S3i, s3, mul2(S3r, c3)),  T3i = f2fma(S3r, n3, mul2(S3i, c3));
        u64 ar = add2(S0r, T2r), ai = add2(S0i, T2i);
        u64 br = f2fma(T2r, NEG1, S0r), bi = f2fma(T2i, NEG1, S0i);
        u64 cr = add2(T1r, T3r), ci = add2(T1i, T3i);
        u64 dr = f2fma(T3r, NEG1, T1r), di = f2fma(T3i, NEG1, T1i);
        u64 Xr[4], Xi4[4];
        Xr[0] = add2(ar, cr);          Xi4[0] = add2(ai, ci);
        Xr[1] = add2(br, di);          Xi4[1] = f2fma(dr, NEG1, bi);
        Xr[2] = f2fma(cr, NEG1, ar);   Xi4[2] = f2fma(ci, NEG1, ai);
        Xr[3] = f2fma(di, NEG1, br);   Xi4[3] = add2(bi, dr);
        #pragma unroll
        for (int p = 0; p < 4; p++) {
            float r0, r1, i0, i1;
            upk2(Xr[p], r0, r1); upk2(Xi4[p], i0, i1);
            int k = e + 12 * p;
            float2 ta = g_tw[k * c2];
            wre[c2 * 52 + k]       = r0 * ta.x + i0 * ta.y;
            wim[c2 * 52 + k]       = i0 * ta.x - r0 * ta.y;
            float2 tb = g_tw[k * (c2 + 1)];
            wre[(c2 + 1) * 52 + k] = r1 * tb.x + i1 * tb.y;
            wim[(c2 + 1) * 52 + k] = i1 * tb.x - r1 * tb.y;
        }
    }
    __syncthreads();

    // ======== stage 2: forward over n2 (complex), rows stride 52; raw Z out ========
    {
        u64 S0r=0,S0i=0,S1r=0,S1i=0,S2r=0,S2i=0,S3r=0,S3i=0;
        int idx = 0;
        #pragma unroll
        for (int m = 0; m < 12; m++) {
            float2 w = w12[idx]; idx += e; if (idx >= 12) idx -= 12;
            u64 cc = pk2(w.x, w.x), ss = pk2(w.y, w.y), ns = pk2(-w.y, -w.y);
            u64 vr0 = *(const u64*)&wre[(4*m+0)*52 + c2], vi0 = *(const u64*)&wim[(4*m+0)*52 + c2];
            u64 vr1 = *(const u64*)&wre[(4*m+1)*52 + c2], vi1 = *(const u64*)&wim[(4*m+1)*52 + c2];
            u64 vr2 = *(const u64*)&wre[(4*m+2)*52 + c2], vi2 = *(const u64*)&wim[(4*m+2)*52 + c2];
            u64 vr3 = *(const u64*)&wre[(4*m+3)*52 + c2], vi3 = *(const u64*)&wim[(4*m+3)*52 + c2];
            S0r = f2fma(vr0, cc, S0r); S0r = f2fma(vi0, ss, S0r);
            S0i = f2fma(vi0, cc, S0i); S0i = f2fma(vr0, ns, S0i);
            S1r = f2fma(vr1, cc, S1r); S1r = f2fma(vi1, ss, S1r);
            S1i = f2fma(vi1, cc, S1i); S1i = f2fma(vr1, ns, S1i);
            S2r = f2fma(vr2, cc, S2r); S2r = f2fma(vi2, ss, S2r);
            S2i = f2fma(vi2, cc, S2i); S2i = f2fma(vr2, ns, S2i);
            S3r = f2fma(vr3, cc, S3r); S3r = f2fma(vi3, ss, S3r);
            S3i = f2fma(vi3, cc, S3i); S3i = f2fma(vr3, ns, S3i);
        }
        u64 T1r = f2fma(S1i, s1, mul2(S1r, c1)),  T1i = f2fma(S1r, n1, mul2(S1i, c1));
        u64 T2r = f2fma(S2i, s2p, mul2(S2r, c2p)), T2i = f2fma(S2r, n2p, mul2(S2i, c2p));
        u64 T3r = f2fma(S3i, s3, mul2(S3r, c3)),  T3i = f2fma(S3r, n3, mul2(S3i, c3));
        u64 ar = add2(S0r, T2r), ai = add2(S0i, T2i);
        u64 br = f2fma(T2r, NEG1, S0r), bi = f2fma(T2i, NEG1, S0i);
        u64 cr = add2(T1r, T3r), ci = add2(T1i, T3i);
        u64 dr = f2fma(T3r, NEG1, T1r), di = f2fma(T3i, NEG1, T1i);
        *(u64*)&bufA[(e     ) * 52 + c2] = add2(ar, cr);
        *(u64*)&Xim [(e     ) * 52 + c2] = add2(ai, ci);
        *(u64*)&bufA[(e + 12) * 52 + c2] = add2(br, di);
        *(u64*)&Xim [(e + 12) * 52 + c2] = f2fma(dr, NEG1, bi);
        *(u64*)&bufA[(e + 24) * 52 + c2] = f2fma(cr, NEG1, ar);
        *(u64*)&Xim [(e + 24) * 52 + c2] = f2fma(ci, NEG1, ai);
        *(u64*)&bufA[(e + 36) * 52 + c2] = f2fma(di, NEG1, br);
        *(u64*)&Xim [(e + 36) * 52 + c2] = add2(bi, dr);
    }
    __syncthreads();

    // ======== mid-pass: Hermitian split, modulate (k <= 1152), repack ========
    {
        const float* fB = g_filt + (long)b * HF + (long)h * FB;
        const float* cB = g_bias + (long)b * HF + (long)h * FB;
        const float sc = 0.5f * inv48;
        for (int k = t; k <= 1152; k += 288) {
            int a = k / 48, bq = k - a * 48;
            int a2, b2q;
            if (bq == 0) { a2 = (48 - a) % 48; b2q = 0; }
            else         { a2 = 47 - a;        b2q = 48 - bq; }
            int i1 = a * 52 + bq, i2 = a2 * 52 + b2q;
            float Zr = bufA[i1], Zi = Xim[i1];
            float Mr = bufA[i2], Mi = Xim[i2];
            float Ar = (Zr + Mr) * sc, Ai = (Zi - Mi) * sc;
            float Br = (Zi + Mi) * sc, Bi = (Mr - Zr) * sc;
            float g = fB[k], cc = cB[k];
            float mr = Ar * g + cc, mi = Ai * g;
            float mag = sqrtf(mr * mr + mi * mi);
            float fac = 0.5f * mag * (1.0f + erff(mag * 0.70710678118654752f))
                        * __fdividef(1.0f, mag + 1e-6f);
            float TAr = mr * fac, TAi = mi * fac;
            mr = Br * g + cc; mi = Bi * g;
            mag = sqrtf(mr * mr + mi * mi);
            fac = 0.5f * mag * (1.0f + erff(mag * 0.70710678118654752f))
                  * __fdividef(1.0f, mag + 1e-6f);
            float TBr = mr * fac, TBi = mi * fac;
            bufA[i1] = TAr - TBi;  Xim[i1] = TAi + TBr;
            bufA[i2] = TAr + TBi;  Xim[i2] = TBr - TAi;
        }
    }
    __syncthreads();

    // ======== stage 3: inverse over k2 (complex), rows stride 52 ========
    {
        u64 S0r=0,S0i=0,S1r=0,S1i=0,S2r=0,S2i=0,S3r=0,S3i=0;
        int idx = 0;
        #pragma unroll
        for (int m = 0; m < 12; m++) {
            float2 w = w12[idx]; idx += e; if (idx >= 12) idx -= 12;
            u64 cc = pk2(w.x, w.x), ss = pk2(w.y, w.y), ns = pk2(-w.y, -w.y);
            u64 vr0 = *(const u64*)&bufA[(4*m+0)*52 + c2], vi0 = *(const u64*)&Xim[(4*m+0)*52 + c2];
            u64 vr1 = *(const u64*)&bufA[(4*m+1)*52 + c2], vi1 = *(const u64*)&Xim[(4*m+1)*52 + c2];
            u64 vr2 = *(const u64*)&bufA[(4*m+2)*52 + c2], vi2 = *(const u64*)&Xim[(4*m+2)*52 + c2];
            u64 vr3 = *(const u64*)&bufA[(4*m+3)*52 + c2], vi3 = *(const u64*)&Xim[(4*m+3)*52 + c2];
            S0r = f2fma(vr0, cc, S0r); S0r = f2fma(vi0, ns, S0r);
            S0i = f2fma(vi0, cc, S0i); S0i = f2fma(vr0, ss, S0i);
            S1r = f2fma(vr1, cc, S1r); S1r = f2fma(vi1, ns, S1r);
            S1i = f2fma(vi1, cc, S1i); S1i = f2fma(vr1, ss, S1i);
            S2r = f2fma(vr2, cc, S2r); S2r = f2fma(vi2, ns, S2r);
            S2i = f2fma(vi2, cc, S2i); S2i = f2fma(vr2, ss, S2i);
            S3r = f2fma(vr3, cc, S3r); S3r = f2fma(vi3, ns, S3r);
            S3i = f2fma(vi3, cc, S3i); S3i = f2fma(vr3, ss, S3i);
        }
        u64 T1r = f2fma(S1i, n1, mul2(S1r, c1)),  T1i = f2fma(S1r, s1, mul2(S1i, c1));
        u64 T2r = f2fma(S2i, n2p, mul2(S2r, c2p)), T2i = f2fma(S2r, s2p, mul2(S2i, c2p));
        u64 T3r = f2fma(S3i, n3, mul2(S3r, c3)),  T3i = f2fma(S3r, s3, mul2(S3i, c3));
        u64 ar = add2(S0r, T2r), ai = add2(S0i, T2i);
        u64 br = f2fma(T2r, NEG1, S0r), bi = f2fma(T2i, NEG1, S0i);
        u64 cr = add2(T1r, T3r), ci = add2(T1i, T3i);
        u64 dr = f2fma(T3r, NEG1, T1r), di = f2fma(T3i, NEG1, T1i);
        u64 Xr[4], Xi4[4];
        Xr[0] = add2(ar, cr);          Xi4[0] = add2(ai, ci);
        Xr[1] = f2fma(di, NEG1, br);   Xi4[1] = add2(bi, dr);          // b + i d
        Xr[2] = f2fma(cr, NEG1, ar);   Xi4[2] = f2fma(ci, NEG1, ai);
        Xr[3] = add2(br, di);          Xi4[3] = f2fma(dr, NEG1, bi);   // b - i d
        #pragma unroll
        for (int p = 0; p < 4; p++) {
            float r0, r1, i0, i1;
            upk2(Xr[p], r0, r1); upk2(Xi4[p], i0, i1);
            int r = e + 12 * p;
            float2 ta = g_tw[r * c2];
            wre[c2 * 52 + r]       = r0 * ta.x - i0 * ta.y;
            wim[c2 * 52 + r]       = r0 * ta.y + i0 * ta.x;
            float2 tb = g_tw[r * (c2 + 1)];
            wre[(c2 + 1) * 52 + r] = r1 * tb.x - i1 * tb.y;
            wim[(c2 + 1) * 52 + r] = r1 * tb.y + i1 * tb.x;
        }
    }
    __syncthreads();

    // ======== stage 4: inverse over k1 (full complex out: re->colA, im->colB) ========
    {
        u64 S0r=0,S0i=0,S1r=0,S1i=0,S2r=0,S2i=0,S3r=0,S3i=0;
        int idx = 0;
        #pragma unroll
        for (int m = 0; m < 12; m++) {
            float2 w = w12[idx]; idx += e; if (idx >= 12) idx -= 12;
            u64 cc = pk2(w.x, w.x), ss = pk2(w.y, w.y), ns = pk2(-w.y, -w.y);
            u64 vr0 = *(const u64*)&wre[(4*m+0)*52 + c2], vi0 = *(const u64*)&wim[(4*m+0)*52 + c2];
            u64 vr1 = *(const u64*)&wre[(4*m+1)*52 + c2], vi1 = *(const u64*)&wim[(4*m+1)*52 + c2];
            u64 vr2 = *(const u64*)&wre[(4*m+2)*52 + c2], vi2 = *(const u64*)&wim[(4*m+2)*52 + c2];
            u64 vr3 = *(const u64*)&wre[(4*m+3)*52 + c2], vi3 = *(const u64*)&wim[(4*m+3)*52 + c2];
            S0r = f2fma(vr0, cc, S0r); S0r = f2fma(vi0, ns, S0r);
            S0i = f2fma(vi0, cc, S0i); S0i = f2fma(vr0, ss, S0i);
            S1r = f2fma(vr1, cc, S1r); S1r = f2fma(vi1, ns, S1r);
            S1i = f2fma(vi1, cc, S1i); S1i = f2fma(vr1, ss, S1i);
            S2r = f2fma(vr2, cc, S2r); S2r = f2fma(vi2, ns, S2r);
            S2i = f2fma(vi2, cc, S2i); S2i = f2fma(vr2, ss, S2i);
            S3r = f2fma(vr3, cc, S3r); S3r = f2fma(vi3, ns, S3r);
            S3i = f2fma(vi3, cc, S3i); S3i = f2fma(vr3, ss, S3i);
        }
        u64 T1r = f2fma(S1i, n1, mul2(S1r, c1)),  T1i = f2fma(S1r, s1, mul2(S1i, c1));
        u64 T2r = f2fma(S2i, n2p, mul2(S2r, c2p)), T2i = f2fma(S2r, s2p, mul2(S2i, c2p));
        u64 T3r = f2fma(S3i, n3, mul2(S3r, c3)),  T3i = f2fma(S3r, s3, mul2(S3i, c3));
        u64 ar = add2(S0r, T2r), ai = add2(S0i, T2i);
        u64 br = f2fma(T2r, NEG1, S0r), bi = f2fma(T2i, NEG1, S0i);
        u64 cr = add2(T1r, T3r), ci = add2(T1i, T3i);
        u64 dr = f2fma(T3r, NEG1, T1r), di = f2fma(T3i, NEG1, T1i);
        u64 I48 = pk2(inv48, inv48);
        float* dstA = g_yt + ((long)b * DD + d0) * NN;
        float* dstB = dstA + NN;
        u64 Xr, Xi;
        Xr = add2(ar, cr);          Xi = add2(ai, ci);
        *(u64*)&dstA[(e     ) * 48 + c2] = mul2(Xr, I48);
        *(u64*)&dstB[(e     ) * 48 + c2] = mul2(Xi, I48);
        Xr = f2fma(di, NEG1, br);   Xi = add2(bi, dr);
        *(u64*)&dstA[(e + 12) * 48 + c2] = mul2(Xr, I48);
        *(u64*)&dstB[(e + 12) * 48 + c2] = mul2(Xi, I48);
        Xr = f2fma(cr, NEG1, ar);   Xi = f2fma(ci, NEG1, ai);
        *(u64*)&dstA[(e + 24) * 48 + c2] = mul2(Xr, I48);
        *(u64*)&dstB[(e + 24) * 48 + c2] = mul2(Xi, I48);
        Xr = add2(br, di);          Xi = f2fma(dr, NEG1, bi);
        *(u64*)&dstA[(e + 36) * 48 + c2] = mul2(Xr, I48);
        *(u64*)&dstB[(e + 36) * 48 + c2] = mul2(Xi, I48);
    }
}

// ---------------- output: out[b][n][d] = x + yt^T (64x64 tiles, float4 I/O) ----------------
__global__ __launch_bounds__(256) void addout_kernel(const float* __restrict__ x,
                                                     float* __restrict__ out) {
    __shared__ float tile[64 * 68];        // [n][d], pad 68 keeps 16B alignment
    int b  = blockIdx.z;
    int n0 = blockIdx.x * 64;
    int d0 = blockIdx.y * 64;
    int t  = threadIdx.x;

    // phase 1: load yt[d][n] (float4 along n) -> tile[n][d]
    {
        int nq = (t & 15) * 4;
        int dr = t >> 4;                   // 16 d-rows per pass
        const float* src = g_yt + ((long)b * DD + d0) * NN + n0;
        #pragma unroll
        for (int p = 0; p < 4; p++) {
            int d = dr + p * 16;
            float4 v = *(const float4*)&src[(long)d * NN + nq];
            tile[(nq + 0) * 68 + d] = v.x;
            tile[(nq + 1) * 68 + d] = v.y;
            tile[(nq + 2) * 68 + d] = v.z;
            tile[(nq + 3) * 68 + d] = v.w;
        }
    }
    __syncthreads();

    // phase 2: out[n][d] = x[n][d] + tile[n][d]  (float4 along d)
    {
        int dq = (t & 15) * 4;
        int nr = t >> 4;
        long base = ((long)b * NN + n0) * DD + d0;
        #pragma unroll
        for (int p = 0; p < 4; p++) {
            int n = nr + p * 16;
            float4 xv = *(const float4*)&x[base + (long)n * DD + dq];
            float4 yv = *(const float4*)&tile[n * 68 + dq];
            float4 ov = make_float4(xv.x + yv.x, xv.y + yv.y, xv.z + yv.z, xv.w + yv.w);
            *(float4*)&out[base + (long)n * DD + dq] = ov;
        }
    }
}

// ---------------- launch ----------------
extern "C" void kernel_launch(void* const* d_in, const int* in_sizes, int n_in,
                              void* d_out, int out_size) {
    const float* x           = (const float*)d_in[0];
    const float* base_filter = (const float*)d_in[1];
    const float* base_bias   = (const float*)d_in[2];
    const float* ln_gamma    = (const float*)d_in[3];
    const float* ln_beta     = (const float*)d_in[4];
    const float* W1          = (const float*)d_in[5];
    const float* b1          = (const float*)d_in[6];
    const float* W2          = (const float*)d_in[7];
    const float* b2          = (const float*)d_in[8];
    float* out = (float*)d_out;

    static bool attr_done = false;
    if (!attr_done) {
        cudaFuncSetAttribute(mlp2_kernel,
                             cudaFuncAttributeMaxDynamicSharedMemorySize, MLP2_SMEM);
        attr_done = true;
    }

    init_kernel<<<32, 256>>>();
    ln_t_kernel<<<dim3(NN / 32, BB), 256>>>(x, ln_gamma, ln_beta);
    mlp1_kernel<<<dim3(BB, 4), 512>>>(W1, b1);
    mlp2_kernel<<<(OUT2 + 63) / 64, 1024, MLP2_SMEM>>>(W2, b2, base_filter, base_bias);
    spectral_kernel<<<BB * DD / 2, 288>>>();
    addout_kernel<<<dim3(NN / 64, DD / 64, BB), 256>>>(x, out);
}